// round 15
// baseline (speedup 1.0000x reference)
#include <cuda_runtime.h>
#include <cstdint>

// Problem constants
#define BB 8
#define CC 256
#define NN 4096
#define DD 128
#define CO 256

// Scratch: device globals (no allocation allowed)
__device__ float g_kq[BB * NN * DD];   // [b][n][k]  16 MB
__device__ float g_v [BB * NN * DD];   // [b][n][c]  16 MB
__device__ float g_ctx[BB * NN * DD];  // [b][n][c]  16 MB

// ---------------------------------------------------------------------------
// Kernel 1: fused kq/v projection.
// kq[b][n][k] = sum_c w_kq[k][c]*x[b][c][n] + b_kq[k];  v likewise.
// CTA: 64 positions x 256 fused output channels (0..127 -> kq, 128..255 -> v).
// Thread microtile 8 out x 8 n. Warp: 4 (out) x 8 (n) lanes; 8 warps along out.
// ---------------------------------------------------------------------------
__global__ void __launch_bounds__(256) proj_kernel(
    const float* __restrict__ x,
    const float* __restrict__ w_kq, const float* __restrict__ b_kq,
    const float* __restrict__ w_v,  const float* __restrict__ b_v)
{
    __shared__ float xs [32][68];    // [c][n]  (natural)
    __shared__ float wst[32][264];   // [c][o]  (transposed weights)

    const int b   = blockIdx.y;
    const int n0  = blockIdx.x * 64;
    const int tid = threadIdx.x;
    const int lane = tid & 31;
    const int wid  = tid >> 5;
    const int lane_o = lane >> 3;          // 0..3
    const int lane_n = lane & 7;           // 0..7
    const int o0 = wid * 32 + lane_o * 8;  // 8 output channels
    const int nt = lane_n * 8;             // 8 positions (within tile)

    float acc[8][8];
#pragma unroll
    for (int a = 0; a < 8; a++)
#pragma unroll
        for (int c = 0; c < 8; c++) acc[a][c] = 0.f;

    const float* xb = x + (size_t)b * CC * NN + n0;

    for (int c0 = 0; c0 < CC; c0 += 32) {
        __syncthreads();
        // load x tile [32 c][64 n], coalesced float4
#pragma unroll
        for (int t = 0; t < 2; t++) {
            int idx = tid + t * 256;            // 0..511 float4s
            int cc = idx >> 4, n4 = idx & 15;
            float4 val = *(const float4*)(xb + (size_t)(c0 + cc) * NN + 4 * n4);
            *(float4*)&xs[cc][4 * n4] = val;
        }
        // load fused weights transposed: wst[c][o]
#pragma unroll
        for (int t = 0; t < 8; t++) {
            int idx = tid + t * 256;            // 0..2047 float4s
            int o = idx >> 3, c4 = idx & 7;
            const float* wsrc = (o < 128) ? (w_kq + (size_t)o * CC)
                                          : (w_v  + (size_t)(o - 128) * CC);
            float4 val = *(const float4*)(wsrc + c0 + 4 * c4);
            wst[4 * c4 + 0][o] = val.x;
            wst[4 * c4 + 1][o] = val.y;
            wst[4 * c4 + 2][o] = val.z;
            wst[4 * c4 + 3][o] = val.w;
        }
        __syncthreads();
#pragma unroll
        for (int cc = 0; cc < 32; cc++) {
            float4 x1 = *(const float4*)&xs[cc][nt];
            float4 x2 = *(const float4*)&xs[cc][nt + 4];
            float4 w1 = *(const float4*)&wst[cc][o0];
            float4 w2 = *(const float4*)&wst[cc][o0 + 4];
            float xr[8] = {x1.x, x1.y, x1.z, x1.w, x2.x, x2.y, x2.z, x2.w};
            float wr[8] = {w1.x, w1.y, w1.z, w1.w, w2.x, w2.y, w2.z, w2.w};
#pragma unroll
            for (int a = 0; a < 8; a++)
#pragma unroll
                for (int c = 0; c < 8; c++)
                    acc[a][c] = fmaf(wr[a], xr[c], acc[a][c]);
        }
    }

    float bias[8];
#pragma unroll
    for (int a = 0; a < 8; a++) {
        int ch = o0 + a;
        bias[a] = (ch < 128) ? b_kq[ch] : b_v[ch - 128];
    }
    float* dstbase = (o0 < 128) ? g_kq : g_v;
    const int od = o0 & 127;
#pragma unroll
    for (int c = 0; c < 8; c++) {
        int n = n0 + nt + c;
        float* dst = dstbase + ((size_t)b * NN + n) * DD + od;
        float4 v1 = make_float4(acc[0][c] + bias[0], acc[1][c] + bias[1],
                                acc[2][c] + bias[2], acc[3][c] + bias[3]);
        float4 v2 = make_float4(acc[4][c] + bias[4], acc[5][c] + bias[5],
                                acc[6][c] + bias[6], acc[7][c] + bias[7]);
        *(float4*)(dst)     = v1;
        *(float4*)(dst + 4) = v2;
    }
}

// ---------------------------------------------------------------------------
// Kernel 2: fused flash attention (no 1/sqrt(d) scaling, Q == K == kq).
// CTA: 128 query rows, streams 64-key tiles, online softmax, O = softmax(S)V.
// Dynamic SMEM layout (floats):
//   Qst[128][132]  (Q transposed: [k][i])
//   Kst[128][65]   (K transposed: [k][j])
//   Vs [64][132]   (natural: [j][c])
//   Pst[64][132]   (P transposed: [j][i])
//   m_s[128], l_s[128], al_s[128], red_m[2][128], red_l[2][128]
// ---------------------------------------------------------------------------
#define OFF_QST 0
#define OFF_KST (128 * 132)
#define OFF_VS  (OFF_KST + 128 * 65)
#define OFF_PST (OFF_VS + 64 * 132)
#define OFF_MS  (OFF_PST + 64 * 132)
#define OFF_LS  (OFF_MS + 128)
#define OFF_AL  (OFF_LS + 128)
#define OFF_RM  (OFF_AL + 128)
#define OFF_RL  (OFF_RM + 256)
#define SMEM_B_FLOATS (OFF_RL + 256)
#define SMEM_B_BYTES  (SMEM_B_FLOATS * 4)

__global__ void __launch_bounds__(256, 1) attn_kernel()
{
    extern __shared__ float sm[];
    float* Qst  = sm + OFF_QST;
    float* Kst  = sm + OFF_KST;
    float* Vs   = sm + OFF_VS;
    float* Pst  = sm + OFF_PST;
    float* m_s  = sm + OFF_MS;
    float* l_s  = sm + OFF_LS;
    float* al_s = sm + OFF_AL;
    float* red_m = sm + OFF_RM;   // [2][128]
    float* red_l = sm + OFF_RL;   // [2][128]

    const int b   = blockIdx.y;
    const int q0  = blockIdx.x * 128;
    const int tid = threadIdx.x;
    const int lane = tid & 31;
    const int wid  = tid >> 5;
    const int warp_i = wid >> 1;           // 0..3
    const int warp_j = wid & 1;            // 0..1
    const int lane_i = lane >> 3;          // 0..3
    const int lane_j = lane & 7;           // 0..7
    const int i0 = warp_i * 32 + lane_i * 8;   // 8 query rows
    const int j0 = warp_j * 32 + lane_j * 4;   // 4 key cols (S phase)
    const int c0 = warp_j * 64 + lane_j * 8;   // 8 value cols (O phase)

    // ---- load Q transposed (once per CTA) ----
    const float* qbase = g_kq + ((size_t)b * NN + q0) * DD;
#pragma unroll
    for (int t = 0; t < 16; t++) {
        int idx = tid + t * 256;            // 0..4095 float4s
        int i = idx >> 5, k4 = idx & 31;
        float4 val = *(const float4*)(qbase + (size_t)i * DD + 4 * k4);
        Qst[(4 * k4 + 0) * 132 + i] = val.x;
        Qst[(4 * k4 + 1) * 132 + i] = val.y;
        Qst[(4 * k4 + 2) * 132 + i] = val.z;
        Qst[(4 * k4 + 3) * 132 + i] = val.w;
    }
    if (tid < 128) { m_s[tid] = -1e30f; l_s[tid] = 0.f; }

    float o[8][8];
#pragma unroll
    for (int a = 0; a < 8; a++)
#pragma unroll
        for (int c = 0; c < 8; c++) o[a][c] = 0.f;

    for (int kt = 0; kt < 64; kt++) {
        __syncthreads();  // prev PV done; Qst/stats ready on first iter
        // ---- load K (transposed) and V (natural) tiles ----
        const float* kb = g_kq + ((size_t)b * NN + kt * 64) * DD;
        const float* vb = g_v  + ((size_t)b * NN + kt * 64) * DD;
#pragma unroll
        for (int t = 0; t < 8; t++) {
            int idx = tid + t * 256;        // 0..2047 float4s
            int j = idx >> 5, k4 = idx & 31;
            float4 kv = *(const float4*)(kb + (size_t)j * DD + 4 * k4);
            Kst[(4 * k4 + 0) * 65 + j] = kv.x;
            Kst[(4 * k4 + 1) * 65 + j] = kv.y;
            Kst[(4 * k4 + 2) * 65 + j] = kv.z;
            Kst[(4 * k4 + 3) * 65 + j] = kv.w;
            float4 vv4 = *(const float4*)(vb + (size_t)j * DD + 4 * k4);
            *(float4*)&Vs[j * 132 + 4 * k4] = vv4;
        }
        __syncthreads();

        // ---- S = Q K^T  (8i x 4j per thread) ----
        float s[8][4];
#pragma unroll
        for (int a = 0; a < 8; a++)
#pragma unroll
            for (int c = 0; c < 4; c++) s[a][c] = 0.f;
#pragma unroll 8
        for (int k = 0; k < 128; k++) {
            float4 q1 = *(const float4*)&Qst[k * 132 + i0];
            float4 q2 = *(const float4*)&Qst[k * 132 + i0 + 4];
            float qr[8] = {q1.x, q1.y, q1.z, q1.w, q2.x, q2.y, q2.z, q2.w};
            float kr0 = Kst[k * 65 + j0 + 0];
            float kr1 = Kst[k * 65 + j0 + 1];
            float kr2 = Kst[k * 65 + j0 + 2];
            float kr3 = Kst[k * 65 + j0 + 3];
#pragma unroll
            for (int a = 0; a < 8; a++) {
                s[a][0] = fmaf(qr[a], kr0, s[a][0]);
                s[a][1] = fmaf(qr[a], kr1, s[a][1]);
                s[a][2] = fmaf(qr[a], kr2, s[a][2]);
                s[a][3] = fmaf(qr[a], kr3, s[a][3]);
            }
        }

        // ---- row max over this key tile ----
        float mp[8];
#pragma unroll
        for (int a = 0; a < 8; a++)
            mp[a] = fmaxf(fmaxf(s[a][0], s[a][1]), fmaxf(s[a][2], s[a][3]));
#pragma unroll
        for (int d = 1; d < 8; d <<= 1)
#pragma unroll
            for (int a = 0; a < 8; a++)
                mp[a] = fmaxf(mp[a], __shfl_xor_sync(0xffffffffu, mp[a], d));
        if (lane_j == 0) {
#pragma unroll
            for (int a = 0; a < 8; a++) red_m[warp_j * 128 + i0 + a] = mp[a];
        }
        __syncthreads();

        // ---- p = exp(s - m_new), row sums ----
        float lsum[8];
#pragma unroll
        for (int a = 0; a < 8; a++) {
            int i = i0 + a;
            float mo = m_s[i];
            float mn = fmaxf(mo, fmaxf(red_m[i], red_m[128 + i]));
            float accp = 0.f;
#pragma unroll
            for (int c = 0; c < 4; c++) {
                float p = __expf(s[a][c] - mn);
                s[a][c] = p;
                accp += p;
            }
            lsum[a] = accp;
        }
#pragma unroll
        for (int d = 1; d < 8; d <<= 1)
#pragma unroll
            for (int a = 0; a < 8; a++)
                lsum[a] += __shfl_xor_sync(0xffffffffu, lsum[a], d);
        if (lane_j == 0) {
#pragma unroll
            for (int a = 0; a < 8; a++) red_l[warp_j * 128 + i0 + a] = lsum[a];
        }
        // ---- store P transposed ----
#pragma unroll
        for (int a = 0; a < 8; a++)
#pragma unroll
            for (int c = 0; c < 4; c++)
                Pst[(j0 + c) * 132 + i0 + a] = s[a][c];
        __syncthreads();

        // ---- update running stats (one owner per row) ----
        if (tid < 128) {
            float mo = m_s[tid];
            float mn = fmaxf(mo, fmaxf(red_m[tid], red_m[128 + tid]));
            float alpha = __expf(mo - mn);
            al_s[tid] = alpha;
            l_s[tid]  = l_s[tid] * alpha + red_l[tid] + red_l[128 + tid];
            m_s[tid]  = mn;
        }
        __syncthreads();

        // ---- rescale O, O += P V  (8i x 8c per thread) ----
        float a8[8];
#pragma unroll
        for (int a = 0; a < 8; a++) a8[a] = al_s[i0 + a];
#pragma unroll
        for (int a = 0; a < 8; a++)
#pragma unroll
            for (int c = 0; c < 8; c++) o[a][c] *= a8[a];
#pragma unroll 4
        for (int j = 0; j < 64; j++) {
            float4 p1 = *(const float4*)&Pst[j * 132 + i0];
            float4 p2 = *(const float4*)&Pst[j * 132 + i0 + 4];
            float4 v1 = *(const float4*)&Vs[j * 132 + c0];
            float4 v2 = *(const float4*)&Vs[j * 132 + c0 + 4];
            float pr[8] = {p1.x, p1.y, p1.z, p1.w, p2.x, p2.y, p2.z, p2.w};
            float vr[8] = {v1.x, v1.y, v1.z, v1.w, v2.x, v2.y, v2.z, v2.w};
#pragma unroll
            for (int a = 0; a < 8; a++)
#pragma unroll
                for (int c = 0; c < 8; c++)
                    o[a][c] = fmaf(pr[a], vr[c], o[a][c]);
        }
    }

    __syncthreads();
    float* cbase = g_ctx + ((size_t)b * NN + q0) * DD;
#pragma unroll
    for (int a = 0; a < 8; a++) {
        int i = i0 + a;
        float linv = 1.0f / l_s[i];
        float4 r1 = make_float4(o[a][0] * linv, o[a][1] * linv,
                                o[a][2] * linv, o[a][3] * linv);
        float4 r2 = make_float4(o[a][4] * linv, o[a][5] * linv,
                                o[a][6] * linv, o[a][7] * linv);
        *(float4*)(cbase + (size_t)i * DD + c0)     = r1;
        *(float4*)(cbase + (size_t)i * DD + c0 + 4) = r2;
    }
}

// ---------------------------------------------------------------------------
// Kernel 3: output projection. out[b][o][n] = sum_v w_o[o][v]*ctx[b][n][v] + b_o[o]
// Same GEMM skeleton as proj_kernel (inner dim 128 in chunks of 32).
// ---------------------------------------------------------------------------
__global__ void __launch_bounds__(256) out_kernel(
    const float* __restrict__ w_o, const float* __restrict__ b_o,
    float* __restrict__ out)
{
    __shared__ float cst[32][68];    // [v][n]  (ctx transposed)
    __shared__ float wst[32][264];   // [v][o]  (w_o transposed)

    const int b   = blockIdx.y;
    const int n0  = blockIdx.x * 64;
    const int tid = threadIdx.x;
    const int lane = tid & 31;
    const int wid  = tid >> 5;
    const int lane_o = lane >> 3;
    const int lane_n = lane & 7;
    const int o0 = wid * 32 + lane_o * 8;
    const int nt = lane_n * 8;

    float acc[8][8];
#pragma unroll
    for (int a = 0; a < 8; a++)
#pragma unroll
        for (int c = 0; c < 8; c++) acc[a][c] = 0.f;

    for (int v0 = 0; v0 < DD; v0 += 32) {
        __syncthreads();
        // ctx tile transposed: [64 n][32 v] -> cst[v][n]
#pragma unroll
        for (int t = 0; t < 2; t++) {
            int idx = tid + t * 256;        // 0..511 float4s
            int n = idx >> 3, v4 = idx & 7;
            float4 cval = *(const float4*)(g_ctx + ((size_t)b * NN + n0 + n) * DD + v0 + 4 * v4);
            cst[4 * v4 + 0][n] = cval.x;
            cst[4 * v4 + 1][n] = cval.y;
            cst[4 * v4 + 2][n] = cval.z;
            cst[4 * v4 + 3][n] = cval.w;
        }
        // w_o tile transposed: [256 o][32 v] -> wst[v][o]
#pragma unroll
        for (int t = 0; t < 8; t++) {
            int idx = tid + t * 256;        // 0..2047 float4s
            int oc = idx >> 3, v4 = idx & 7;
            float4 wv = *(const float4*)(w_o + (size_t)oc * DD + v0 + 4 * v4);
            wst[4 * v4 + 0][oc] = wv.x;
            wst[4 * v4 + 1][oc] = wv.y;
            wst[4 * v4 + 2][oc] = wv.z;
            wst[4 * v4 + 3][oc] = wv.w;
        }
        __syncthreads();
#pragma unroll
        for (int vv = 0; vv < 32; vv++) {
            float4 x1 = *(const float4*)&cst[vv][nt];
            float4 x2 = *(const float4*)&cst[vv][nt + 4];
            float4 w1 = *(const float4*)&wst[vv][o0];
            float4 w2 = *(const float4*)&wst[vv][o0 + 4];
            float xr[8] = {x1.x, x1.y, x1.z, x1.w, x2.x, x2.y, x2.z, x2.w};
            float wr[8] = {w1.x, w1.y, w1.z, w1.w, w2.x, w2.y, w2.z, w2.w};
#pragma unroll
            for (int a = 0; a < 8; a++)
#pragma unroll
                for (int c = 0; c < 8; c++)
                    acc[a][c] = fmaf(wr[a], xr[c], acc[a][c]);
        }
    }

#pragma unroll
    for (int a = 0; a < 8; a++) {
        int oc = o0 + a;
        float bo = b_o[oc];
        float4 r1 = make_float4(acc[a][0] + bo, acc[a][1] + bo,
                                acc[a][2] + bo, acc[a][3] + bo);
        float4 r2 = make_float4(acc[a][4] + bo, acc[a][5] + bo,
                                acc[a][6] + bo, acc[a][7] + bo);
        float* dst = out + ((size_t)b * CO + oc) * NN + n0 + nt;
        *(float4*)(dst)     = r1;
        *(float4*)(dst + 4) = r2;
    }
}

// ---------------------------------------------------------------------------
extern "C" void kernel_launch(void* const* d_in, const int* in_sizes, int n_in,
                              void* d_out, int out_size)
{
    (void)in_sizes; (void)n_in; (void)out_size;
    const float* x    = (const float*)d_in[0];
    const float* w_kq = (const float*)d_in[1];
    const float* b_kq = (const float*)d_in[2];
    const float* w_v  = (const float*)d_in[3];
    const float* b_v  = (const float*)d_in[4];
    const float* w_o  = (const float*)d_in[5];
    const float* b_o  = (const float*)d_in[6];
    float* out = (float*)d_out;

    // Opt in to large dynamic shared memory for the attention kernel.
    // (Attribute set, not a stream op; safe under graph capture, idempotent.)
    cudaFuncSetAttribute(attn_kernel,
                         cudaFuncAttributeMaxDynamicSharedMemorySize,
                         SMEM_B_BYTES);

    proj_kernel<<<dim3(NN / 64, BB), 256>>>(x, w_kq, b_kq, w_v, b_v);
    attn_kernel<<<dim3(NN / 128, BB), 256, SMEM_B_BYTES>>>();
    out_kernel<<<dim3(NN / 64, BB), 256>>>(w_o, b_o, out);
}

// round 16
// speedup vs baseline: 1.0009x; 1.0009x over previous
#include <cuda_runtime.h>
#include <cstdint>

// Problem constants
#define BB 8
#define CC 256
#define NN 4096
#define DD 128
#define CO 256

// Scratch: device globals (no allocation allowed)
__device__ float g_kq[BB * NN * DD];   // [b][n][k]  16 MB
__device__ float g_v [BB * NN * DD];   // [b][n][c]  16 MB
__device__ float g_ctx[BB * NN * DD];  // [b][n][c]  16 MB

// ---------------------------------------------------------------------------
// Kernel 1: fused kq/v projection.
// kq[b][n][k] = sum_c w_kq[k][c]*x[b][c][n] + b_kq[k];  v likewise.
// CTA: 64 positions x 256 fused output channels (0..127 -> kq, 128..255 -> v).
// Thread microtile 8 out x 8 n. Warp: 4 (out) x 8 (n) lanes; 8 warps along out.
// ---------------------------------------------------------------------------
__global__ void __launch_bounds__(256) proj_kernel(
    const float* __restrict__ x,
    const float* __restrict__ w_kq, const float* __restrict__ b_kq,
    const float* __restrict__ w_v,  const float* __restrict__ b_v)
{
    __shared__ float xs [32][68];    // [c][n]  (natural)
    __shared__ float wst[32][264];   // [c][o]  (transposed weights)

    const int b   = blockIdx.y;
    const int n0  = blockIdx.x * 64;
    const int tid = threadIdx.x;
    const int lane = tid & 31;
    const int wid  = tid >> 5;
    const int lane_o = lane >> 3;          // 0..3
    const int lane_n = lane & 7;           // 0..7
    const int o0 = wid * 32 + lane_o * 8;  // 8 output channels
    const int nt = lane_n * 8;             // 8 positions (within tile)

    float acc[8][8];
#pragma unroll
    for (int a = 0; a < 8; a++)
#pragma unroll
        for (int c = 0; c < 8; c++) acc[a][c] = 0.f;

    const float* xb = x + (size_t)b * CC * NN + n0;

    for (int c0 = 0; c0 < CC; c0 += 32) {
        __syncthreads();
        // load x tile [32 c][64 n], coalesced float4
#pragma unroll
        for (int t = 0; t < 2; t++) {
            int idx = tid + t * 256;            // 0..511 float4s
            int cc = idx >> 4, n4 = idx & 15;
            float4 val = *(const float4*)(xb + (size_t)(c0 + cc) * NN + 4 * n4);
            *(float4*)&xs[cc][4 * n4] = val;
        }
        // load fused weights transposed: wst[c][o]
#pragma unroll
        for (int t = 0; t < 8; t++) {
            int idx = tid + t * 256;            // 0..2047 float4s
            int o = idx >> 3, c4 = idx & 7;
            const float* wsrc = (o < 128) ? (w_kq + (size_t)o * CC)
                                          : (w_v  + (size_t)(o - 128) * CC);
            float4 val = *(const float4*)(wsrc + c0 + 4 * c4);
            wst[4 * c4 + 0][o] = val.x;
            wst[4 * c4 + 1][o] = val.y;
            wst[4 * c4 + 2][o] = val.z;
            wst[4 * c4 + 3][o] = val.w;
        }
        __syncthreads();
#pragma unroll
        for (int cc = 0; cc < 32; cc++) {
            float4 x1 = *(const float4*)&xs[cc][nt];
            float4 x2 = *(const float4*)&xs[cc][nt + 4];
            float4 w1 = *(const float4*)&wst[cc][o0];
            float4 w2 = *(const float4*)&wst[cc][o0 + 4];
            float xr[8] = {x1.x, x1.y, x1.z, x1.w, x2.x, x2.y, x2.z, x2.w};
            float wr[8] = {w1.x, w1.y, w1.z, w1.w, w2.x, w2.y, w2.z, w2.w};
#pragma unroll
            for (int a = 0; a < 8; a++)
#pragma unroll
                for (int c = 0; c < 8; c++)
                    acc[a][c] = fmaf(wr[a], xr[c], acc[a][c]);
        }
    }

    float bias[8];
#pragma unroll
    for (int a = 0; a < 8; a++) {
        int ch = o0 + a;
        bias[a] = (ch < 128) ? b_kq[ch] : b_v[ch - 128];
    }
    float* dstbase = (o0 < 128) ? g_kq : g_v;
    const int od = o0 & 127;
#pragma unroll
    for (int c = 0; c < 8; c++) {
        int n = n0 + nt + c;
        float* dst = dstbase + ((size_t)b * NN + n) * DD + od;
        float4 v1 = make_float4(acc[0][c] + bias[0], acc[1][c] + bias[1],
                                acc[2][c] + bias[2], acc[3][c] + bias[3]);
        float4 v2 = make_float4(acc[4][c] + bias[4], acc[5][c] + bias[5],
                                acc[6][c] + bias[6], acc[7][c] + bias[7]);
        *(float4*)(dst)     = v1;
        *(float4*)(dst + 4) = v2;
    }
}

// ---------------------------------------------------------------------------
// Kernel 2: fused flash attention (no 1/sqrt(d) scaling, Q == K == kq).
// CTA: 128 query rows, streams 64-key tiles, online softmax, O = softmax(S)V.
// Dynamic SMEM layout (floats):
//   Qst[128][132]  (Q transposed: [k][i])
//   Kst[128][65]   (K transposed: [k][j])
//   Vs [64][132]   (natural: [j][c])
//   Pst[64][132]   (P transposed: [j][i])
//   m_s[128], l_s[128], al_s[128], red_m[2][128], red_l[2][128]
// ---------------------------------------------------------------------------
#define OFF_QST 0
#define OFF_KST (128 * 132)
#define OFF_VS  (OFF_KST + 128 * 65)
#define OFF_PST (OFF_VS + 64 * 132)
#define OFF_MS  (OFF_PST + 64 * 132)
#define OFF_LS  (OFF_MS + 128)
#define OFF_AL  (OFF_LS + 128)
#define OFF_RM  (OFF_AL + 128)
#define OFF_RL  (OFF_RM + 256)
#define SMEM_B_FLOATS (OFF_RL + 256)
#define SMEM_B_BYTES  (SMEM_B_FLOATS * 4)

__global__ void __launch_bounds__(256, 1) attn_kernel()
{
    extern __shared__ float sm[];
    float* Qst  = sm + OFF_QST;
    float* Kst  = sm + OFF_KST;
    float* Vs   = sm + OFF_VS;
    float* Pst  = sm + OFF_PST;
    float* m_s  = sm + OFF_MS;
    float* l_s  = sm + OFF_LS;
    float* al_s = sm + OFF_AL;
    float* red_m = sm + OFF_RM;   // [2][128]
    float* red_l = sm + OFF_RL;   // [2][128]

    const int b   = blockIdx.y;
    const int q0  = blockIdx.x * 128;
    const int tid = threadIdx.x;
    const int lane = tid & 31;
    const int wid  = tid >> 5;
    const int warp_i = wid >> 1;           // 0..3
    const int warp_j = wid & 1;            // 0..1
    const int lane_i = lane >> 3;          // 0..3
    const int lane_j = lane & 7;           // 0..7
    const int i0 = warp_i * 32 + lane_i * 8;   // 8 query rows
    const int j0 = warp_j * 32 + lane_j * 4;   // 4 key cols (S phase)
    const int c0 = warp_j * 64 + lane_j * 8;   // 8 value cols (O phase)

    // ---- load Q transposed (once per CTA) ----
    const float* qbase = g_kq + ((size_t)b * NN + q0) * DD;
#pragma unroll
    for (int t = 0; t < 16; t++) {
        int idx = tid + t * 256;            // 0..4095 float4s
        int i = idx >> 5, k4 = idx & 31;
        float4 val = *(const float4*)(qbase + (size_t)i * DD + 4 * k4);
        Qst[(4 * k4 + 0) * 132 + i] = val.x;
        Qst[(4 * k4 + 1) * 132 + i] = val.y;
        Qst[(4 * k4 + 2) * 132 + i] = val.z;
        Qst[(4 * k4 + 3) * 132 + i] = val.w;
    }
    if (tid < 128) { m_s[tid] = -1e30f; l_s[tid] = 0.f; }

    float o[8][8];
#pragma unroll
    for (int a = 0; a < 8; a++)
#pragma unroll
        for (int c = 0; c < 8; c++) o[a][c] = 0.f;

    for (int kt = 0; kt < 64; kt++) {
        __syncthreads();  // prev PV done; Qst/stats ready on first iter
        // ---- load K (transposed) and V (natural) tiles ----
        const float* kb = g_kq + ((size_t)b * NN + kt * 64) * DD;
        const float* vb = g_v  + ((size_t)b * NN + kt * 64) * DD;
#pragma unroll
        for (int t = 0; t < 8; t++) {
            int idx = tid + t * 256;        // 0..2047 float4s
            int j = idx >> 5, k4 = idx & 31;
            float4 kv = *(const float4*)(kb + (size_t)j * DD + 4 * k4);
            Kst[(4 * k4 + 0) * 65 + j] = kv.x;
            Kst[(4 * k4 + 1) * 65 + j] = kv.y;
            Kst[(4 * k4 + 2) * 65 + j] = kv.z;
            Kst[(4 * k4 + 3) * 65 + j] = kv.w;
            float4 vv4 = *(const float4*)(vb + (size_t)j * DD + 4 * k4);
            *(float4*)&Vs[j * 132 + 4 * k4] = vv4;
        }
        __syncthreads();

        // ---- S = Q K^T  (8i x 4j per thread) ----
        float s[8][4];
#pragma unroll
        for (int a = 0; a < 8; a++)
#pragma unroll
            for (int c = 0; c < 4; c++) s[a][c] = 0.f;
#pragma unroll 8
        for (int k = 0; k < 128; k++) {
            float4 q1 = *(const float4*)&Qst[k * 132 + i0];
            float4 q2 = *(const float4*)&Qst[k * 132 + i0 + 4];
            float qr[8] = {q1.x, q1.y, q1.z, q1.w, q2.x, q2.y, q2.z, q2.w};
            float kr0 = Kst[k * 65 + j0 + 0];
            float kr1 = Kst[k * 65 + j0 + 1];
            float kr2 = Kst[k * 65 + j0 + 2];
            float kr3 = Kst[k * 65 + j0 + 3];
#pragma unroll
            for (int a = 0; a < 8; a++) {
                s[a][0] = fmaf(qr[a], kr0, s[a][0]);
                s[a][1] = fmaf(qr[a], kr1, s[a][1]);
                s[a][2] = fmaf(qr[a], kr2, s[a][2]);
                s[a][3] = fmaf(qr[a], kr3, s[a][3]);
            }
        }

        // ---- row max over this key tile ----
        float mp[8];
#pragma unroll
        for (int a = 0; a < 8; a++)
            mp[a] = fmaxf(fmaxf(s[a][0], s[a][1]), fmaxf(s[a][2], s[a][3]));
#pragma unroll
        for (int d = 1; d < 8; d <<= 1)
#pragma unroll
            for (int a = 0; a < 8; a++)
                mp[a] = fmaxf(mp[a], __shfl_xor_sync(0xffffffffu, mp[a], d));
        if (lane_j == 0) {
#pragma unroll
            for (int a = 0; a < 8; a++) red_m[warp_j * 128 + i0 + a] = mp[a];
        }
        __syncthreads();

        // ---- p = exp(s - m_new), row sums ----
        float lsum[8];
#pragma unroll
        for (int a = 0; a < 8; a++) {
            int i = i0 + a;
            float mo = m_s[i];
            float mn = fmaxf(mo, fmaxf(red_m[i], red_m[128 + i]));
            float accp = 0.f;
#pragma unroll
            for (int c = 0; c < 4; c++) {
                float p = __expf(s[a][c] - mn);
                s[a][c] = p;
                accp += p;
            }
            lsum[a] = accp;
        }
#pragma unroll
        for (int d = 1; d < 8; d <<= 1)
#pragma unroll
            for (int a = 0; a < 8; a++)
                lsum[a] += __shfl_xor_sync(0xffffffffu, lsum[a], d);
        if (lane_j == 0) {
#pragma unroll
            for (int a = 0; a < 8; a++) red_l[warp_j * 128 + i0 + a] = lsum[a];
        }
        // ---- store P transposed ----
#pragma unroll
        for (int a = 0; a < 8; a++)
#pragma unroll
            for (int c = 0; c < 4; c++)
                Pst[(j0 + c) * 132 + i0 + a] = s[a][c];
        __syncthreads();

        // ---- update running stats (one owner per row) ----
        if (tid < 128) {
            float mo = m_s[tid];
            float mn = fmaxf(mo, fmaxf(red_m[tid], red_m[128 + tid]));
            float alpha = __expf(mo - mn);
            al_s[tid] = alpha;
            l_s[tid]  = l_s[tid] * alpha + red_l[tid] + red_l[128 + tid];
            m_s[tid]  = mn;
        }
        __syncthreads();

        // ---- rescale O, O += P V  (8i x 8c per thread) ----
        float a8[8];
#pragma unroll
        for (int a = 0; a < 8; a++) a8[a] = al_s[i0 + a];
#pragma unroll
        for (int a = 0; a < 8; a++)
#pragma unroll
            for (int c = 0; c < 8; c++) o[a][c] *= a8[a];
#pragma unroll 4
        for (int j = 0; j < 64; j++) {
            float4 p1 = *(const float4*)&Pst[j * 132 + i0];
            float4 p2 = *(const float4*)&Pst[j * 132 + i0 + 4];
            float4 v1 = *(const float4*)&Vs[j * 132 + c0];
            float4 v2 = *(const float4*)&Vs[j * 132 + c0 + 4];
            float pr[8] = {p1.x, p1.y, p1.z, p1.w, p2.x, p2.y, p2.z, p2.w};
            float vr[8] = {v1.x, v1.y, v1.z, v1.w, v2.x, v2.y, v2.z, v2.w};
#pragma unroll
            for (int a = 0; a < 8; a++)
#pragma unroll
                for (int c = 0; c < 8; c++)
                    o[a][c] = fmaf(pr[a], vr[c], o[a][c]);
        }
    }

    __syncthreads();
    float* cbase = g_ctx + ((size_t)b * NN + q0) * DD;
#pragma unroll
    for (int a = 0; a < 8; a++) {
        int i = i0 + a;
        float linv = 1.0f / l_s[i];
        float4 r1 = make_float4(o[a][0] * linv, o[a][1] * linv,
                                o[a][2] * linv, o[a][3] * linv);
        float4 r2 = make_float4(o[a][4] * linv, o[a][5] * linv,
                                o[a][6] * linv, o[a][7] * linv);
        *(float4*)(cbase + (size_t)i * DD + c0)     = r1;
        *(float4*)(cbase + (size_t)i * DD + c0 + 4) = r2;
    }
}

// ---------------------------------------------------------------------------
// Kernel 3: output projection. out[b][o][n] = sum_v w_o[o][v]*ctx[b][n][v] + b_o[o]
// Same GEMM skeleton as proj_kernel (inner dim 128 in chunks of 32).
// ---------------------------------------------------------------------------
__global__ void __launch_bounds__(256) out_kernel(
    const float* __restrict__ w_o, const float* __restrict__ b_o,
    float* __restrict__ out)
{
    __shared__ float cst[32][68];    // [v][n]  (ctx transposed)
    __shared__ float wst[32][264];   // [v][o]  (w_o transposed)

    const int b   = blockIdx.y;
    const int n0  = blockIdx.x * 64;
    const int tid = threadIdx.x;
    const int lane = tid & 31;
    const int wid  = tid >> 5;
    const int lane_o = lane >> 3;
    const int lane_n = lane & 7;
    const int o0 = wid * 32 + lane_o * 8;
    const int nt = lane_n * 8;

    float acc[8][8];
#pragma unroll
    for (int a = 0; a < 8; a++)
#pragma unroll
        for (int c = 0; c < 8; c++) acc[a][c] = 0.f;

    for (int v0 = 0; v0 < DD; v0 += 32) {
        __syncthreads();
        // ctx tile transposed: [64 n][32 v] -> cst[v][n]
#pragma unroll
        for (int t = 0; t < 2; t++) {
            int idx = tid + t * 256;        // 0..511 float4s
            int n = idx >> 3, v4 = idx & 7;
            float4 cval = *(const float4*)(g_ctx + ((size_t)b * NN + n0 + n) * DD + v0 + 4 * v4);
            cst[4 * v4 + 0][n] = cval.x;
            cst[4 * v4 + 1][n] = cval.y;
            cst[4 * v4 + 2][n] = cval.z;
            cst[4 * v4 + 3][n] = cval.w;
        }
        // w_o tile transposed: [256 o][32 v] -> wst[v][o]
#pragma unroll
        for (int t = 0; t < 8; t++) {
            int idx = tid + t * 256;        // 0..2047 float4s
            int oc = idx >> 3, v4 = idx & 7;
            float4 wv = *(const float4*)(w_o + (size_t)oc * DD + v0 + 4 * v4);
            wst[4 * v4 + 0][oc] = wv.x;
            wst[4 * v4 + 1][oc] = wv.y;
            wst[4 * v4 + 2][oc] = wv.z;
            wst[4 * v4 + 3][oc] = wv.w;
        }
        __syncthreads();
#pragma unroll
        for (int vv = 0; vv < 32; vv++) {
            float4 x1 = *(const float4*)&cst[vv][nt];
            float4 x2 = *(const float4*)&cst[vv][nt + 4];
            float4 w1 = *(const float4*)&wst[vv][o0];
            float4 w2 = *(const float4*)&wst[vv][o0 + 4];
            float xr[8] = {x1.x, x1.y, x1.z, x1.w, x2.x, x2.y, x2.z, x2.w};
            float wr[8] = {w1.x, w1.y, w1.z, w1.w, w2.x, w2.y, w2.z, w2.w};
#pragma unroll
            for (int a = 0; a < 8; a++)
#pragma unroll
                for (int c = 0; c < 8; c++)
                    acc[a][c] = fmaf(wr[a], xr[c], acc[a][c]);
        }
    }

#pragma unroll
    for (int a = 0; a < 8; a++) {
        int oc = o0 + a;
        float bo = b_o[oc];
        float4 r1 = make_float4(acc[a][0] + bo, acc[a][1] + bo,
                                acc[a][2] + bo, acc[a][3] + bo);
        float4 r2 = make_float4(acc[a][4] + bo, acc[a][5] + bo,
                                acc[a][6] + bo, acc[a][7] + bo);
        float* dst = out + ((size_t)b * CO + oc) * NN + n0 + nt;
        *(float4*)(dst)     = r1;
        *(float4*)(dst + 4) = r2;
    }
}

// ---------------------------------------------------------------------------
extern "C" void kernel_launch(void* const* d_in, const int* in_sizes, int n_in,
                              void* d_out, int out_size)
{
    (void)in_sizes; (void)n_in; (void)out_size;
    const float* x    = (const float*)d_in[0];
    const float* w_kq = (const float*)d_in[1];
    const float* b_kq = (const float*)d_in[2];
    const float* w_v  = (const float*)d_in[3];
    const float* b_v  = (const float*)d_in[4];
    const float* w_o  = (const float*)d_in[5];
    const float* b_o  = (const float*)d_in[6];
    float* out = (float*)d_out;

    // Opt in to large dynamic shared memory for the attention kernel.
    // (Attribute set, not a stream op; safe under graph capture, idempotent.)
    cudaFuncSetAttribute(attn_kernel,
                         cudaFuncAttributeMaxDynamicSharedMemorySize,
                         SMEM_B_BYTES);

    proj_kernel<<<dim3(NN / 64, BB), 256>>>(x, w_kq, b_kq, w_v, b_v);
    attn_kernel<<<dim3(NN / 128, BB), 256, SMEM_B_BYTES>>>();
    out_kernel<<<dim3(NN / 64, BB), 256>>>(w_o, b_o, out);
}